// round 1
// baseline (speedup 1.0000x reference)
#include <cuda_runtime.h>
#include <cstdint>
#include <cstddef>

#define MD 28          // matrix dim
#define D  784         // MD*MD
#define SEQ 128        // sequence length
#define NCHUNK 4       // chain chunks (associativity split)
#define CLEN 32        // SEQ/NCHUNK == warp size (one word index per lane)
#define MAXB 512

// Scratch for chunk partial products (no cudaMalloc allowed).
__device__ float g_partials[(size_t)MAXB * NCHUNK * D];

// ---------- packed f32x2 helpers (Blackwell; full fp32 precision, 2 FMA/instr) ----------
__device__ __forceinline__ unsigned long long pack2(float lo, float hi) {
    unsigned long long r;
    asm("mov.b64 %0, {%1, %2};" : "=l"(r) : "f"(lo), "f"(hi));
    return r;
}
__device__ __forceinline__ void unpack2(unsigned long long v, float& lo, float& hi) {
    asm("mov.b64 {%0, %1}, %2;" : "=f"(lo), "=f"(hi) : "l"(v));
}
__device__ __forceinline__ unsigned long long mul2(unsigned long long a, unsigned long long b) {
    unsigned long long r;
    asm("mul.rn.f32x2 %0, %1, %2;" : "=l"(r) : "l"(a), "l"(b));
    return r;
}
__device__ __forceinline__ void fma2(unsigned long long& d, unsigned long long a, unsigned long long b) {
    asm("fma.rn.f32x2 %0, %1, %2, %0;" : "+l"(d) : "l"(a), "l"(b));
}

// cur (row i of the running product, 28 fp32 in regs) *= W  (W: 784 floats, row-major,
// read identically by all lanes -> broadcast loads).
__device__ __forceinline__ void mm_step(float c[MD], const float4* __restrict__ w) {
    unsigned long long n2[14];
    #pragma unroll
    for (int k = 0; k < MD; ++k) {
        unsigned long long ck2 = pack2(c[k], c[k]);
        #pragma unroll
        for (int q = 0; q < 7; ++q) {
            float4 wv = __ldg(w + k * 7 + q);
            unsigned long long wlo = pack2(wv.x, wv.y);
            unsigned long long whi = pack2(wv.z, wv.w);
            if (k == 0) {
                n2[2*q]   = mul2(ck2, wlo);
                n2[2*q+1] = mul2(ck2, whi);
            } else {
                fma2(n2[2*q],   ck2, wlo);
                fma2(n2[2*q+1], ck2, whi);
            }
        }
    }
    #pragma unroll
    for (int q = 0; q < 14; ++q) unpack2(n2[q], c[2*q], c[2*q+1]);
}

// Phase 1: one warp per (batch, chunk). Product of 32 consecutive word matrices.
__global__ void __launch_bounds__(128)
w2m_phase1(const int* __restrict__ sent, const float* __restrict__ tab, int B)
{
    int gw   = (int)((blockIdx.x * blockDim.x + threadIdx.x) >> 5);
    int lane = (int)(threadIdx.x & 31);
    int b = gw / NCHUNK, chunk = gw % NCHUNK;
    if (b >= B) return;

    // one word index per lane for this chunk
    int idx = sent[b * SEQ + chunk * CLEN + lane];
    int i = (lane < MD) ? lane : 0;   // lanes 28..31 shadow row 0 (stores predicated off)

    // cur = first matrix of the chunk; lane i loads its own row (coalesced)
    const float4* w0 =
        (const float4*)(tab + (size_t)__shfl_sync(0xffffffffu, idx, 0) * D);
    float c[MD];
    #pragma unroll
    for (int q = 0; q < 7; ++q) {
        float4 v = __ldg(w0 + i * 7 + q);
        c[4*q] = v.x; c[4*q+1] = v.y; c[4*q+2] = v.z; c[4*q+3] = v.w;
    }

    for (int s = 1; s < CLEN; ++s) {
        const float4* w =
            (const float4*)(tab + (size_t)__shfl_sync(0xffffffffu, idx, s) * D);
        mm_step(c, w);
    }

    if (lane < MD) {
        float4* p = (float4*)(g_partials + (size_t)(b * NCHUNK + chunk) * D + (size_t)i * MD);
        #pragma unroll
        for (int q = 0; q < 7; ++q)
            p[q] = make_float4(c[4*q], c[4*q+1], c[4*q+2], c[4*q+3]);
    }
}

// Phase 2: one warp per batch. out = P0 * P1 * P2 * P3.
__global__ void __launch_bounds__(128)
w2m_phase2(float* __restrict__ out, int B)
{
    int b    = (int)((blockIdx.x * blockDim.x + threadIdx.x) >> 5);
    int lane = (int)(threadIdx.x & 31);
    if (b >= B) return;
    int i = (lane < MD) ? lane : 0;

    const float4* p0 = (const float4*)(g_partials + (size_t)(b * NCHUNK) * D);
    float c[MD];
    #pragma unroll
    for (int q = 0; q < 7; ++q) {
        float4 v = __ldg(p0 + i * 7 + q);
        c[4*q] = v.x; c[4*q+1] = v.y; c[4*q+2] = v.z; c[4*q+3] = v.w;
    }

    #pragma unroll
    for (int p = 1; p < NCHUNK; ++p) {
        const float4* w = (const float4*)(g_partials + (size_t)(b * NCHUNK + p) * D);
        mm_step(c, w);
    }

    if (lane < MD) {
        float4* o = (float4*)(out + (size_t)b * D + (size_t)i * MD);
        #pragma unroll
        for (int q = 0; q < 7; ++q)
            o[q] = make_float4(c[4*q], c[4*q+1], c[4*q+2], c[4*q+3]);
    }
}

extern "C" void kernel_launch(void* const* d_in, const int* in_sizes, int n_in,
                              void* d_out, int out_size)
{
    // sent is the small int tensor (B*S), emb_table the big float one; guard on order.
    const int*   sent;
    const float* tab;
    if (in_sizes[0] < in_sizes[1]) {
        sent = (const int*)d_in[0];
        tab  = (const float*)d_in[1];
    } else {
        sent = (const int*)d_in[1];
        tab  = (const float*)d_in[0];
    }
    int B = out_size / D;   // 512
    if (B > MAXB) B = MAXB;

    int threads1 = B * NCHUNK * 32;                 // one warp per (batch, chunk)
    w2m_phase1<<<(threads1 + 127) / 128, 128>>>(sent, tab, B);

    int threads2 = B * 32;                          // one warp per batch
    w2m_phase2<<<(threads2 + 127) / 128, 128>>>((float*)d_out, B);
}

// round 4
// speedup vs baseline: 2.5765x; 2.5765x over previous
#include <cuda_runtime.h>
#include <cstdint>
#include <cstddef>

#define MD   28          // matrix dim
#define D    784         // MD*MD
#define SEQ  128         // sequence length
#define NW   4           // warps per block == chain chunks
#define CLEN 32          // SEQ/NW == warp size (one word index per lane)

// ---------- packed f32x2 helpers (full fp32 precision, 2 FMA/instr) ----------
__device__ __forceinline__ unsigned long long pack2(float lo, float hi) {
    unsigned long long r;
    asm("mov.b64 %0, {%1, %2};" : "=l"(r) : "f"(lo), "f"(hi));
    return r;
}
__device__ __forceinline__ void unpack2(unsigned long long v, float& lo, float& hi) {
    asm("mov.b64 {%0, %1}, %2;" : "=f"(lo), "=f"(hi) : "l"(v));
}
__device__ __forceinline__ unsigned long long mul2(unsigned long long a, unsigned long long b) {
    unsigned long long r;
    asm("mul.rn.f32x2 %0, %1, %2;" : "=l"(r) : "l"(a), "l"(b));
    return r;
}
__device__ __forceinline__ void fma2(unsigned long long& d, unsigned long long a, unsigned long long b) {
    asm("fma.rn.f32x2 %0, %1, %2, %0;" : "+l"(d) : "l"(a), "l"(b));
}

// ---------- cp.async (LDGSTS) helpers ----------
__device__ __forceinline__ void cp16(void* dst_smem, const void* src_gmem) {
    unsigned s = (unsigned)__cvta_generic_to_shared(dst_smem);
    asm volatile("cp.async.cg.shared.global [%0], [%1], 16;\n"
                 :: "r"(s), "l"(src_gmem) : "memory");
}
__device__ __forceinline__ void cp_commit() {
    asm volatile("cp.async.commit_group;\n" ::: "memory");
}
template <int N>
__device__ __forceinline__ void cp_wait() {
    asm volatile("cp.async.wait_group %0;\n" :: "n"(N) : "memory");
}

// cur (row i of running product, in regs) *= W, W in SHARED memory (broadcast LDS.128).
__device__ __forceinline__ void mm_step_s(float c[MD], const float4* __restrict__ w) {
    unsigned long long n2[14];
    #pragma unroll
    for (int k = 0; k < MD; ++k) {
        unsigned long long ck2 = pack2(c[k], c[k]);
        #pragma unroll
        for (int q = 0; q < 7; ++q) {
            float4 wv = w[k * 7 + q];
            unsigned long long wlo = pack2(wv.x, wv.y);
            unsigned long long whi = pack2(wv.z, wv.w);
            if (k == 0) {
                n2[2*q]   = mul2(ck2, wlo);
                n2[2*q+1] = mul2(ck2, whi);
            } else {
                fma2(n2[2*q],   ck2, wlo);
                fma2(n2[2*q+1], ck2, whi);
            }
        }
    }
    #pragma unroll
    for (int q = 0; q < 14; ++q) unpack2(n2[q], c[2*q], c[2*q+1]);
}

__device__ __forceinline__ void store_rows_f4(float4* dst7, const float c[MD]) {
    #pragma unroll
    for (int q = 0; q < 7; ++q)
        dst7[q] = make_float4(c[4*q], c[4*q+1], c[4*q+2], c[4*q+3]);
}

// Fused: one block per batch. 4 warps, each computes the product of its
// 32-matrix chunk with cp.async double-buffered weight staging; then a
// 2-level smem tree combines the 4 partials and warp 0 writes the result.
__global__ void __launch_bounds__(NW * 32)
w2m_fused(const int* __restrict__ sent, const float* __restrict__ tab,
          float* __restrict__ out)
{
    // per-warp double buffer: 196 float4 = 3136 B per stage
    __shared__ float4 sbuf[NW][2][196];

    int b    = blockIdx.x;
    int w    = (int)(threadIdx.x >> 5);
    int lane = (int)(threadIdx.x & 31);
    int i    = (lane < MD) ? lane : 0;   // lanes 28..31 shadow row 0

    // one word index per lane for this warp's chunk
    int idx = sent[b * SEQ + w * CLEN + lane];

    // prefetch matrix for step 1 into buffer 1 (all 32 lanes cooperate);
    // issued FIRST so the LDGSTS stream overlaps the row-0 load below.
    {
        int idx1 = __shfl_sync(0xffffffffu, idx, 1);
        const char* src = (const char*)(tab + (size_t)idx1 * D);
        char* dst = (char*)&sbuf[w][1][0];
        #pragma unroll
        for (int t = 0; t < 7; ++t) {
            int j = lane + 32 * t;
            if (j < 196) cp16(dst + j * 16, src + j * 16);
        }
        cp_commit();
    }

    // c = row i of matrix 0 (direct coalesced global load, latency paid once)
    float c[MD];
    {
        int idx0 = __shfl_sync(0xffffffffu, idx, 0);
        const float4* w0 = (const float4*)(tab + (size_t)idx0 * D) + i * 7;
        #pragma unroll
        for (int q = 0; q < 7; ++q) {
            float4 v = __ldg(w0 + q);
            c[4*q] = v.x; c[4*q+1] = v.y; c[4*q+2] = v.z; c[4*q+3] = v.w;
        }
    }

    #pragma unroll 1
    for (int s = 1; s < CLEN; ++s) {
        if (s + 1 < CLEN) {
            // issue prefetch for step s+1 into the other buffer
            int idxn = __shfl_sync(0xffffffffu, idx, s + 1);
            const char* src = (const char*)(tab + (size_t)idxn * D);
            char* dst = (char*)&sbuf[w][(s + 1) & 1][0];
            #pragma unroll
            for (int t = 0; t < 7; ++t) {
                int j = lane + 32 * t;
                if (j < 196) cp16(dst + j * 16, src + j * 16);
            }
            cp_commit();
            cp_wait<1>();          // matrix for step s has landed
        } else {
            cp_wait<0>();
        }
        __syncwarp();
        mm_step_s(c, &sbuf[w][s & 1][0]);
    }

    // ---- combine tree: P0*P1, P2*P3, then product of those ----
    if (lane < MD)
        store_rows_f4((float4*)((float*)&sbuf[w][0][0] + i * MD), c);
    __syncthreads();

    if (w == 0) {
        mm_step_s(c, &sbuf[1][0][0]);                 // c = P0 * P1
    } else if (w == 2) {
        mm_step_s(c, &sbuf[3][0][0]);                 // c = P2 * P3
        if (lane < MD)
            store_rows_f4((float4*)((float*)&sbuf[2][0][0] + i * MD), c);
    }
    __syncthreads();

    if (w == 0) {
        mm_step_s(c, &sbuf[2][0][0]);                 // c = (P0P1) * (P2P3)
        if (lane < MD)
            store_rows_f4((float4*)(out + (size_t)b * D + (size_t)i * MD), c);
    }
}

extern "C" void kernel_launch(void* const* d_in, const int* in_sizes, int n_in,
                              void* d_out, int out_size)
{
    const int*   sent;
    const float* tab;
    if (in_sizes[0] < in_sizes[1]) {
        sent = (const int*)d_in[0];
        tab  = (const float*)d_in[1];
    } else {
        sent = (const int*)d_in[1];
        tab  = (const float*)d_in[0];
    }
    int B = out_size / D;   // 512
    w2m_fused<<<B, NW * 32>>>(sent, tab, (float*)d_out);
}

// round 5
// speedup vs baseline: 2.5895x; 1.0050x over previous
#include <cuda_runtime.h>
#include <cstdint>
#include <cstddef>

#define MD   28          // matrix dim
#define D    784         // MD*MD
#define SEQ  128         // sequence length
#define NW   4           // warps per block == chain chunks
#define CLEN 32          // SEQ/NW == warp size (one word index per lane)
#define MAT_BYTES 3136   // D * 4

// ---------- packed f32x2 helpers (full fp32 precision, 2 FMA/instr) ----------
__device__ __forceinline__ unsigned long long pack2(float lo, float hi) {
    unsigned long long r;
    asm("mov.b64 %0, {%1, %2};" : "=l"(r) : "f"(lo), "f"(hi));
    return r;
}
__device__ __forceinline__ void unpack2(unsigned long long v, float& lo, float& hi) {
    asm("mov.b64 {%0, %1}, %2;" : "=f"(lo), "=f"(hi) : "l"(v));
}
__device__ __forceinline__ unsigned long long mul2(unsigned long long a, unsigned long long b) {
    unsigned long long r;
    asm("mul.rn.f32x2 %0, %1, %2;" : "=l"(r) : "l"(a), "l"(b));
    return r;
}
__device__ __forceinline__ void fma2(unsigned long long& d, unsigned long long a, unsigned long long b) {
    asm("fma.rn.f32x2 %0, %1, %2, %0;" : "+l"(d) : "l"(a), "l"(b));
}

// ---------- TMA bulk-copy + mbarrier helpers ----------
__device__ __forceinline__ unsigned s2u(const void* p) {
    return (unsigned)__cvta_generic_to_shared(p);
}
__device__ __forceinline__ void mbar_init(void* mbar) {
    asm volatile("mbarrier.init.shared.b64 [%0], %1;"
                 :: "r"(s2u(mbar)), "r"(1u) : "memory");
}
__device__ __forceinline__ void mbar_expect_tx(void* mbar, unsigned bytes) {
    asm volatile("mbarrier.arrive.expect_tx.shared.b64 _, [%0], %1;"
                 :: "r"(s2u(mbar)), "r"(bytes) : "memory");
}
__device__ __forceinline__ void mbar_wait(void* mbar, unsigned parity) {
    asm volatile(
        "{\n\t"
        ".reg .pred P;\n"
        "W%=:\n\t"
        "mbarrier.try_wait.parity.acquire.cta.shared::cta.b64 P, [%0], %1, 0x989680;\n\t"
        "@P bra D%=;\n\t"
        "bra W%=;\n"
        "D%=:\n\t"
        "}"
        :: "r"(s2u(mbar)), "r"(parity) : "memory");
}
// one instruction moves a whole 3136-B matrix global -> smem
__device__ __forceinline__ void bulk_cp(void* dst_smem, const void* src_gmem,
                                        unsigned bytes, void* mbar) {
    asm volatile(
        "cp.async.bulk.shared::cta.global.mbarrier::complete_tx::bytes [%0], [%1], %2, [%3];"
        :: "r"(s2u(dst_smem)), "l"(src_gmem), "r"(bytes), "r"(s2u(mbar)) : "memory");
}
__device__ __forceinline__ void fence_proxy_async_cta() {
    asm volatile("fence.proxy.async.shared::cta;" ::: "memory");
}

// cur (row i of running product, in regs) *= W, W in SHARED memory (broadcast LDS.128).
__device__ __forceinline__ void mm_step_s(float c[MD], const float4* __restrict__ w) {
    unsigned long long n2[14];
    #pragma unroll
    for (int k = 0; k < MD; ++k) {
        unsigned long long ck2 = pack2(c[k], c[k]);
        #pragma unroll
        for (int q = 0; q < 7; ++q) {
            float4 wv = w[k * 7 + q];
            unsigned long long wlo = pack2(wv.x, wv.y);
            unsigned long long whi = pack2(wv.z, wv.w);
            if (k == 0) {
                n2[2*q]   = mul2(ck2, wlo);
                n2[2*q+1] = mul2(ck2, whi);
            } else {
                fma2(n2[2*q],   ck2, wlo);
                fma2(n2[2*q+1], ck2, whi);
            }
        }
    }
    #pragma unroll
    for (int q = 0; q < 14; ++q) unpack2(n2[q], c[2*q], c[2*q+1]);
}

__device__ __forceinline__ void store_rows_f4(float4* dst7, const float c[MD]) {
    #pragma unroll
    for (int q = 0; q < 7; ++q)
        dst7[q] = make_float4(c[4*q], c[4*q+1], c[4*q+2], c[4*q+3]);
}

// One block per batch. 4 warps, each computes its 32-matrix chunk product with a
// private TMA-bulk-copy double-buffered pipeline; 2-level smem tree combines.
__global__ void __launch_bounds__(NW * 32)
w2m_fused(const int* __restrict__ sent, const float* __restrict__ tab,
          float* __restrict__ out)
{
    __shared__ float4 sbuf[NW][2][196];                 // 2-stage weight buffers per warp
    __shared__ __align__(8) unsigned long long mbar[NW][2];

    int b    = blockIdx.x;
    int w    = (int)(threadIdx.x >> 5);
    int lane = (int)(threadIdx.x & 31);
    int i    = (lane < MD) ? lane : 0;   // lanes 28..31 shadow row 0

    // init this warp's mbarriers (lane 0), make visible to the async proxy
    if (lane == 0) {
        mbar_init(&mbar[w][0]);
        mbar_init(&mbar[w][1]);
        fence_proxy_async_cta();
    }
    __syncwarp();

    // one word index per lane for this warp's chunk
    int idx = sent[b * SEQ + w * CLEN + lane];

    // kick off TMA for step 1 into buffer 1 before anything else
    if (lane == 0) {
        int idx1 = __shfl_sync(0x1u, idx, 1);  // lane0 already has full idx vector? no: shuffle below
    }
    // (shuffle must be warp-wide; redo properly)
    {
        int idx1 = __shfl_sync(0xffffffffu, idx, 1);
        if (lane == 0) {
            mbar_expect_tx(&mbar[w][1], MAT_BYTES);
            bulk_cp(&sbuf[w][1][0], tab + (size_t)idx1 * D, MAT_BYTES, &mbar[w][1]);
        }
    }

    // c = row i of matrix 0 (direct coalesced global load, latency paid once)
    float c[MD];
    {
        int idx0 = __shfl_sync(0xffffffffu, idx, 0);
        const float4* w0 = (const float4*)(tab + (size_t)idx0 * D) + i * 7;
        #pragma unroll
        for (int q = 0; q < 7; ++q) {
            float4 v = __ldg(w0 + q);
            c[4*q] = v.x; c[4*q+1] = v.y; c[4*q+2] = v.z; c[4*q+3] = v.w;
        }
    }

    unsigned ph0 = 0, ph1 = 0;   // per-buffer phase parity

    #pragma unroll 1
    for (int s = 1; s < CLEN; ++s) {
        if (s + 1 < CLEN) {
            // prefetch step s+1 into the other buffer (single TMA by lane 0)
            int idxn = __shfl_sync(0xffffffffu, idx, s + 1);
            if (lane == 0) {
                void* mb = &mbar[w][(s + 1) & 1];
                mbar_expect_tx(mb, MAT_BYTES);
                bulk_cp(&sbuf[w][(s + 1) & 1][0], tab + (size_t)idxn * D, MAT_BYTES, mb);
            }
        }
        // wait for the matrix of step s
        if (s & 1) { mbar_wait(&mbar[w][1], ph1); ph1 ^= 1u; }
        else       { mbar_wait(&mbar[w][0], ph0); ph0 ^= 1u; }
        mm_step_s(c, &sbuf[w][s & 1][0]);
    }

    // ---- combine tree: P0*P1, P2*P3, then product of those ----
    if (lane < MD)
        store_rows_f4((float4*)((float*)&sbuf[w][0][0] + i * MD), c);
    __syncthreads();

    if (w == 0) {
        mm_step_s(c, &sbuf[1][0][0]);                 // c = P0 * P1
    } else if (w == 2) {
        mm_step_s(c, &sbuf[3][0][0]);                 // c = P2 * P3
        if (lane < MD)
            store_rows_f4((float4*)((float*)&sbuf[2][0][0] + i * MD), c);
    }
    __syncthreads();

    if (w == 0) {
        mm_step_s(c, &sbuf[2][0][0]);                 // c = (P0P1) * (P2P3)
        if (lane < MD)
            store_rows_f4((float4*)(out + (size_t)b * D + (size_t)i * MD), c);
    }
}

extern "C" void kernel_launch(void* const* d_in, const int* in_sizes, int n_in,
                              void* d_out, int out_size)
{
    const int*   sent;
    const float* tab;
    if (in_sizes[0] < in_sizes[1]) {
        sent = (const int*)d_in[0];
        tab  = (const float*)d_in[1];
    } else {
        sent = (const int*)d_in[1];
        tab  = (const float*)d_in[0];
    }
    int B = out_size / D;   // 512
    w2m_fused<<<B, NW * 32>>>(sent, tab, (float*)d_out);
}